// round 17
// baseline (speedup 1.0000x reference)
#include <cuda_runtime.h>
#include <cuda_bf16.h>
#include <cstdint>

// Problem constants
#define B_   2
#define N_   4096
#define E_   256
#define H_   8
#define TAU_ 32
#define HD_  32
#define M_   (B_ * N_)
#define SCALING 0.17677669529663687f
#define XSZ  ((size_t)M_ * E_)

// Scratch: projected Q, K, V (fp32) + preconverted W (bf16 hi/lo)
__device__ float g_proj[3 * XSZ];
__device__ __align__(16) __nv_bfloat16 g_wh[E_ * E_];
__device__ __align__(16) __nv_bfloat16 g_wl[E_ * E_];

// ---------------------------------------------------------------------------
__device__ __forceinline__ uint32_t smem_u32(const void* p) {
    uint32_t a;
    asm("{ .reg .u64 t; cvta.to.shared.u64 t, %1; cvt.u32.u64 %0, t; }"
        : "=r"(a) : "l"(p));
    return a;
}

__device__ __forceinline__ void split_bf16(float x, __nv_bfloat16& h,
                                           __nv_bfloat16& l) {
    h = __float2bfloat16(x);
    l = __float2bfloat16(x - __bfloat162float(h));
}

__device__ __forceinline__ void mma_bf16(float c[4], const uint32_t a[4],
                                         const uint32_t b[2]) {
    asm volatile(
        "mma.sync.aligned.m16n8k16.row.col.f32.bf16.bf16.f32 "
        "{%0,%1,%2,%3}, {%4,%5,%6,%7}, {%8,%9}, {%0,%1,%2,%3};"
        : "+f"(c[0]), "+f"(c[1]), "+f"(c[2]), "+f"(c[3])
        : "r"(a[0]), "r"(a[1]), "r"(a[2]), "r"(a[3]), "r"(b[0]), "r"(b[1]));
}

#define LDSM_X4(R0, R1, R2, R3, ADDR)                                          \
    asm volatile("ldmatrix.sync.aligned.m8n8.x4.shared.b16 {%0,%1,%2,%3}, [%4];" \
                 : "=r"(R0), "=r"(R1), "=r"(R2), "=r"(R3) : "r"(ADDR))

// ---------------------------------------------------------------------------
// W preconversion: 256x256 fp32 -> bf16 hi + lo. Tiny (~65K elems).
// ---------------------------------------------------------------------------
__global__ __launch_bounds__(256) void convert_w_kernel(const float* __restrict__ W) {
    int i = blockIdx.x * 256 + threadIdx.x;     // float4 index
    if (i >= E_ * E_ / 4) return;
    float4 v = *reinterpret_cast<const float4*>(W + 4 * i);
    __nv_bfloat16 h[4], l[4];
    split_bf16(v.x, h[0], l[0]);
    split_bf16(v.y, h[1], l[1]);
    split_bf16(v.z, h[2], l[2]);
    split_bf16(v.w, h[3], l[3]);
    *reinterpret_cast<ushort4*>(&g_wh[4 * i]) =
        make_ushort4(__bfloat16_as_ushort(h[0]), __bfloat16_as_ushort(h[1]),
                     __bfloat16_as_ushort(h[2]), __bfloat16_as_ushort(h[3]));
    *reinterpret_cast<ushort4*>(&g_wl[4 * i]) =
        make_ushort4(__bfloat16_as_ushort(l[0]), __bfloat16_as_ushort(l[1]),
                     __bfloat16_as_ushort(l[2]), __bfloat16_as_ushort(l[3]));
}

// ---------------------------------------------------------------------------
// Projection GEMM: P = X @ W^T + bias (M=8192, N=256, K=256), z selects X.
// Block 128x64, BK=32, 8 warps (4M x 2N), warp tile 32x32, split-3 bf16.
// A staging: round-13 inline split. B staging: pure uint4 copies from
// preconverted g_wh/g_wl. Fragments: ldmatrix.x4, SST=40 (bank-exact).
// ---------------------------------------------------------------------------
#define SST 40

__global__ __launch_bounds__(256) void proj_kernel(
        const float* __restrict__ Q,
        const float* __restrict__ K,
        const float* __restrict__ V,
        const float* __restrict__ bias) {
    __shared__ alignas(16) __nv_bfloat16 sAh[128 * SST];
    __shared__ alignas(16) __nv_bfloat16 sAl[128 * SST];
    __shared__ alignas(16) __nv_bfloat16 sBh[64 * SST];
    __shared__ alignas(16) __nv_bfloat16 sBl[64 * SST];

    const float* X = (blockIdx.z == 0) ? Q : (blockIdx.z == 1 ? K : V);
    float* P = g_proj + (size_t)blockIdx.z * XSZ;

    const int tid  = threadIdx.x;
    const int m0   = blockIdx.y << 7;
    const int n0   = blockIdx.x << 6;
    const int lane = tid & 31;
    const int warp = tid >> 5;
    const int g    = lane >> 2;
    const int tig  = lane & 3;
    const int wM   = warp & 3;
    const int wN   = warp >> 2;

    const uint32_t bAh = smem_u32(sAh), bAl = smem_u32(sAl);
    const uint32_t bBh = smem_u32(sBh), bBl = smem_u32(sBl);
    const int aoff = (lane & 15) * SST + ((lane >> 4) << 3);
    const int boff = ((lane & 7) + ((lane & 16) >> 1)) * SST
                   + (((lane >> 3) & 1) << 3);

    // B staging coords (fixed): row = tid>>2, 8 cols from (tid&3)*8
    const int brow = tid >> 2;
    const int bc8  = (tid & 3) << 3;

    float acc[2][4][4];
    #pragma unroll
    for (int mi = 0; mi < 2; mi++)
        #pragma unroll
        for (int ni = 0; ni < 4; ni++)
            #pragma unroll
            for (int r = 0; r < 4; r++) acc[mi][ni][r] = 0.f;

    #pragma unroll 1
    for (int k0 = 0; k0 < E_; k0 += 32) {
        __syncthreads();
        // Stage A chunk 128x32: inline split, 4 float4 per thread
        #pragma unroll
        for (int i = 0; i < 4; i++) {
            int e   = tid + (i << 8);
            int row = e >> 3;
            int c4  = (e & 7) << 2;
            float4 v = *reinterpret_cast<const float4*>(
                &X[(size_t)(m0 + row) * E_ + k0 + c4]);
            __nv_bfloat16 h[4], l[4];
            split_bf16(v.x, h[0], l[0]);
            split_bf16(v.y, h[1], l[1]);
            split_bf16(v.z, h[2], l[2]);
            split_bf16(v.w, h[3], l[3]);
            int o = row * SST + c4;
            *reinterpret_cast<ushort4*>(&sAh[o]) =
                make_ushort4(__bfloat16_as_ushort(h[0]), __bfloat16_as_ushort(h[1]),
                             __bfloat16_as_ushort(h[2]), __bfloat16_as_ushort(h[3]));
            *reinterpret_cast<ushort4*>(&sAl[o]) =
                make_ushort4(__bfloat16_as_ushort(l[0]), __bfloat16_as_ushort(l[1]),
                             __bfloat16_as_ushort(l[2]), __bfloat16_as_ushort(l[3]));
        }
        // Stage B chunk 64x32: pure 16B copies from preconverted W
        {
            size_t so = (size_t)(n0 + brow) * E_ + k0 + bc8;
            int   dd  = brow * SST + bc8;
            *reinterpret_cast<uint4*>(&sBh[dd]) =
                *reinterpret_cast<const uint4*>(&g_wh[so]);
            *reinterpret_cast<uint4*>(&sBl[dd]) =
                *reinterpret_cast<const uint4*>(&g_wl[so]);
        }
        __syncthreads();

        #pragma unroll
        for (int kk = 0; kk < 32; kk += 16) {
            uint32_t ah[2][4], al[2][4], bh[4][2], bl[4][2];
            #pragma unroll
            for (int mi = 0; mi < 2; mi++) {
                uint32_t ea = 2u * (uint32_t)((wM * 32 + mi * 16) * SST + aoff + kk);
                LDSM_X4(ah[mi][0], ah[mi][1], ah[mi][2], ah[mi][3], bAh + ea);
                LDSM_X4(al[mi][0], al[mi][1], al[mi][2], al[mi][3], bAl + ea);
            }
            #pragma unroll
            for (int p = 0; p < 2; p++) {
                uint32_t eb = 2u * (uint32_t)((wN * 32 + p * 16) * SST + boff + kk);
                LDSM_X4(bh[2*p][0], bh[2*p][1], bh[2*p+1][0], bh[2*p+1][1], bBh + eb);
                LDSM_X4(bl[2*p][0], bl[2*p][1], bl[2*p+1][0], bl[2*p+1][1], bBl + eb);
            }
            #pragma unroll
            for (int mi = 0; mi < 2; mi++)
                #pragma unroll
                for (int ni = 0; ni < 4; ni++) {
                    mma_bf16(acc[mi][ni], ah[mi], bh[ni]);
                    mma_bf16(acc[mi][ni], ah[mi], bl[ni]);
                    mma_bf16(acc[mi][ni], al[mi], bh[ni]);
                }
        }
    }

    #pragma unroll
    for (int mi = 0; mi < 2; mi++) {
        int row = m0 + wM * 32 + mi * 16 + g;
        #pragma unroll
        for (int ni = 0; ni < 4; ni++) {
            int col = n0 + wN * 32 + ni * 8 + tig * 2;
            float2 bb = *reinterpret_cast<const float2*>(&bias[col]);
            float2 o0 = {acc[mi][ni][0] + bb.x, acc[mi][ni][1] + bb.y};
            float2 o1 = {acc[mi][ni][2] + bb.x, acc[mi][ni][3] + bb.y};
            *reinterpret_cast<float2*>(&P[(size_t)row       * E_ + col]) = o0;
            *reinterpret_cast<float2*>(&P[(size_t)(row + 8) * E_ + col]) = o1;
        }
    }
}

// ---------------------------------------------------------------------------
// Sliding-window attention (round-16 structure) with forced occupancy:
// __launch_bounds__(256, 5) caps regs at 51 -> 5 blocks/SM (was 4).
// ---------------------------------------------------------------------------
__global__ __launch_bounds__(256, 5) void attn_kernel(
        const float* __restrict__ bias,
        float* __restrict__ out) {
    const int QT = 64, ROWS = QT + TAU_ - 1, S = 36, PW = 38;

    __shared__ float sK[ROWS][S];
    __shared__ float sV[ROWS][S];
    __shared__ float sP[QT][PW];     // prob at [q][3 + t]; borders zero

    const int tid  = threadIdx.x;
    const int tile = blockIdx.x & 63;
    const int h    = (blockIdx.x >> 6) & 7;
    const int b    = blockIdx.x >> 9;
    const int n0   = tile * QT;
    const int be   = h * HD_;

    const float* Qp = g_proj;
    const float* Kp = g_proj + XSZ;
    const float* Vp = g_proj + 2 * XSZ;

    // Zero sP (covers pad borders)
    for (int i = tid; i < QT * PW / 2; i += 256)
        *reinterpret_cast<float2*>(&sP[0][0] + 2 * i) = make_float2(0.f, 0.f);

    // Stage K/V window rows [n0-31, n0+63]; pre-sequence rows = bias vector.
    for (int i = tid; i < ROWS * 8; i += 256) {
        int row = i >> 3, c = i & 7;
        int r = n0 - (TAU_ - 1) + row;
        float4 kv, vv;
        if (r >= 0) {
            size_t off = ((size_t)(b * N_ + r)) * E_ + be;
            kv = reinterpret_cast<const float4*>(&Kp[off])[c];
            vv = reinterpret_cast<const float4*>(&Vp[off])[c];
        } else {
            kv = reinterpret_cast<const float4*>(&bias[be])[c];
            vv = kv;
        }
        *reinterpret_cast<float4*>(&sK[row][c << 2]) = kv;
        *reinterpret_cast<float4*>(&sV[row][c << 2]) = vv;
    }
    __syncthreads();

    // ---- Score phase: 2-query pairing (round-10 validated) ----
    const int p   = tid >> 3;        // pair 0..31
    const int sub = tid & 7;         // 0..7
    const int lq0 = p << 1;
    const int t0  = sub << 2;

    float d0[5] = {0.f, 0.f, 0.f, 0.f, 0.f};
    float d1[5] = {0.f, 0.f, 0.f, 0.f, 0.f};
    const float* q0p = &Qp[((size_t)(b * N_ + n0 + lq0)) * E_ + be];
    #pragma unroll
    for (int c = 0; c < 4; c++) {
        float4 qa0 = *reinterpret_cast<const float4*>(q0p + (c << 3));
        float4 qa1 = *reinterpret_cast<const float4*>(q0p + (c << 3) + 4);
        float4 qb0 = *reinterpret_cast<const float4*>(q0p + E_ + (c << 3));
        float4 qb1 = *reinterpret_cast<const float4*>(q0p + E_ + (c << 3) + 4);
        #pragma unroll
        for (int j = 0; j < 5; j++) {
            const float* kr = &sK[lq0 + t0 + j][c << 3];
            float4 k0v = *reinterpret_cast<const float4*>(kr);
            float4 k1v = *reinterpret_cast<const float4*>(kr + 4);
            d0[j] += qa0.x * k0v.x + qa0.y * k0v.y + qa0.z * k0v.z + qa0.w * k0v.w
                   + qa1.x * k1v.x + qa1.y * k1v.y + qa1.z * k1v.z + qa1.w * k1v.w;
            d1[j] += qb0.x * k0v.x + qb0.y * k0v.y + qb0.z * k0v.z + qb0.w * k0v.w
                   + qb1.x * k1v.x + qb1.y * k1v.y + qb1.z * k1v.z + qb1.w * k1v.w;
        }
    }
    float s0[4], s1[4];
    #pragma unroll
    for (int j = 0; j < 4; j++) {
        s0[j] = d0[j] * SCALING;
        s1[j] = d1[j + 1] * SCALING;
    }

    float mx0 = fmaxf(fmaxf(s0[0], s0[1]), fmaxf(s0[2], s0[3]));
    float mx1 = fmaxf(fmaxf(s1[0], s1[1]), fmaxf(s1[2], s1[3]));
    #pragma unroll
    for (int m = 1; m <= 4; m <<= 1) {
        mx0 = fmaxf(mx0, __shfl_xor_sync(0xffffffffu, mx0, m));
        mx1 = fmaxf(mx1, __shfl_xor_sync(0xffffffffu, mx1, m));
    }
    float sum0 = 0.f, sum1 = 0.f;
    #pragma unroll
    for (int j = 0; j < 4; j++) {
        s0[j] = __expf(s0[j] - mx0); sum0 += s0[j];
        s1[j] = __expf(s1[j] - mx1); sum1 += s1[j];
    }
    #pragma unroll
    for (int m = 1; m <= 4; m <<= 1) {
        sum0 += __shfl_xor_sync(0xffffffffu, sum0, m);
        sum1 += __shfl_xor_sync(0xffffffffu, sum1, m);
    }
    float inv0 = 1.f / sum0, inv1 = 1.f / sum1;
    #pragma unroll
    for (int j = 0; j < 4; j++) {
        sP[lq0][3 + t0 + j]     = s0[j] * inv0;
        sP[lq0 + 1][3 + t0 + j] = s1[j] * inv1;
    }
    __syncthreads();

    // ---- Output phase: quad mapping, 4 queries x 2 dims per thread ----
    const int quad = tid >> 4;        // 0..15
    const int q0   = quad << 2;       // query base
    const int d0c  = (tid & 15) << 1; // dim base (float2)

    float2 o[4];
    #pragma unroll
    for (int qi = 0; qi < 4; qi++) o[qi] = make_float2(0.f, 0.f);

    #pragma unroll
    for (int rr = 0; rr < 35; rr++) {
        float2 v = *reinterpret_cast<const float2*>(&sV[q0 + rr][d0c]);
        #pragma unroll
        for (int qi = 0; qi < 4; qi++) {
            float pr = sP[q0 + qi][3 + rr - qi];  // zero outside valid band
            o[qi].x += pr * v.x;
            o[qi].y += pr * v.y;
        }
    }

    #pragma unroll
    for (int qi = 0; qi < 4; qi++) {
        float* orow = &out[((size_t)(b * N_ + n0 + q0 + qi)) * E_ + be + d0c];
        *reinterpret_cast<float2*>(orow) = o[qi];
    }
}

// ---------------------------------------------------------------------------
// Launch
// ---------------------------------------------------------------------------
extern "C" void kernel_launch(void* const* d_in, const int* in_sizes, int n_in,
                              void* d_out, int out_size) {
    const float* query = (const float*)d_in[0];
    const float* key   = (const float*)d_in[1];
    const float* value = (const float*)d_in[2];
    const float* W     = (const float*)d_in[3];
    const float* bias  = (const float*)d_in[4];
    float* out = (float*)d_out;

    convert_w_kernel<<<E_ * E_ / 4 / 256, 256>>>(W);

    dim3 gProj(E_ / 64, M_ / 128, 3);   // (4, 64, 3)
    proj_kernel<<<gProj, 256>>>(query, key, value, bias);

    attn_kernel<<<B_ * H_ * (N_ / 64), 256>>>(bias, out);
}